// round 1
// baseline (speedup 1.0000x reference)
#include <cuda_runtime.h>
#include <cstdint>

#define N_NODES 100000
#define N_EDGES 3200000
#define F_IN 64
#define HID 20
#define N_GRAPHS 128
#define N_CLASSES 10
#define EPS_NORM 1e-12f

// ---------------- scratch (device globals; no allocation allowed) ----------
__device__ __align__(16) float g_y[N_NODES * HID];    // pre-multiplied features (x@Wa or h@Wa)
__device__ __align__(16) float g_agg[N_NODES * HID];  // scatter-add destination
__device__ __align__(16) float g_h[N_NODES * HID];    // final layer node embeddings
__device__ float g_pmax[N_GRAPHS * HID];
__device__ float g_psum[N_GRAPHS * HID];
__device__ float g_cnt[N_GRAPHS];
__device__ int   g_is64;                              // 1 if indices are int64, 0 if int32

// ---------------- dtype probe ---------------------------------------------
__global__ void k_detect(const void* __restrict__ ei) {
    if (threadIdx.x == 0 && blockIdx.x == 0) {
        const long long* p = (const long long*)ei;
        bool ok = true;
        #pragma unroll
        for (int i = 0; i < 16; i++) {
            long long v = p[i];
            if (v < 0 || v >= (long long)N_NODES) ok = false;
        }
        g_is64 = ok ? 1 : 0;
    }
}

// ---------------- zero kernels --------------------------------------------
__global__ void k_zero_agg() {
    int i = blockIdx.x * blockDim.x + threadIdx.x;
    if (i < N_NODES * HID) g_agg[i] = 0.0f;
}

__global__ void k_zero_pool() {
    int i = blockIdx.x * blockDim.x + threadIdx.x;
    if (i < N_GRAPHS * HID) { g_pmax[i] = 0.0f; g_psum[i] = 0.0f; }
    if (i < N_GRAPHS) g_cnt[i] = 0.0f;
}

// ---------------- layer-1 input GEMM: y = x @ W1a  (N x 64 @ 64 x 20) -----
#define GEMM_NPB 12
__global__ void k_gemm_in(const float* __restrict__ x, const float* __restrict__ W) {
    __shared__ float Ws[F_IN * HID];       // 64*20
    __shared__ float xs[GEMM_NPB * F_IN];  // 12*64
    int tid = threadIdx.x;
    for (int i = tid; i < F_IN * HID; i += blockDim.x) Ws[i] = W[i];
    int nbase = blockIdx.x * GEMM_NPB;
    int cnt = N_NODES - nbase; if (cnt > GEMM_NPB) cnt = GEMM_NPB;
    for (int i = tid; i < cnt * F_IN; i += blockDim.x) xs[i] = x[nbase * F_IN + i];
    __syncthreads();
    if (tid < cnt * HID) {
        int ln = tid / HID, f = tid % HID;
        float acc = 0.0f;
        #pragma unroll
        for (int k = 0; k < F_IN; k++) acc += xs[ln * F_IN + k] * Ws[k * HID + f];
        g_y[nbase * HID + tid] = acc;
    }
}

// ---------------- scatter: agg[dst] += y[src] * w --------------------------
__global__ void k_scatter(const void* __restrict__ ei, const float* __restrict__ w) {
    int e = blockIdx.x * blockDim.x + threadIdx.x;
    if (e >= N_EDGES) return;
    long long s, d;
    if (g_is64) {
        const long long* p = (const long long*)ei;
        s = p[e]; d = p[N_EDGES + e];
    } else {
        const int* p = (const int*)ei;
        s = p[e]; d = p[N_EDGES + e];
    }
    float wt = w[e];
    const float4* yr = (const float4*)(g_y + s * HID);
    float* ar = g_agg + d * HID;
    #pragma unroll
    for (int i = 0; i < 5; i++) {
        float4 v = __ldg(yr + i);
        asm volatile("red.global.add.v4.f32 [%0], {%1,%2,%3,%4};"
                     :: "l"(ar + i * 4),
                        "f"(v.x * wt), "f"(v.y * wt), "f"(v.z * wt), "f"(v.w * wt)
                     : "memory");
    }
}

// ---------------- node MLP: z=relu(agg+ba); z=relu(z@Wb+bb); L2norm; relu;
//                  out = h@Wn (if Wn) else h ------------------------------
__global__ void k_mlp(const float* __restrict__ ba, const float* __restrict__ Wb,
                      const float* __restrict__ bb, const float* __restrict__ Wn,
                      int write_h) {
    __shared__ float sWb[HID * HID], sWn[HID * HID], sba[HID], sbb[HID];
    int tid = threadIdx.x;
    for (int i = tid; i < HID * HID; i += blockDim.x) {
        sWb[i] = Wb[i];
        sWn[i] = Wn ? Wn[i] : 0.0f;
    }
    if (tid < HID) { sba[tid] = ba[tid]; sbb[tid] = bb[tid]; }
    __syncthreads();
    int n = blockIdx.x * blockDim.x + tid;
    if (n >= N_NODES) return;

    float4 t[5];
    const float4* ag = (const float4*)(g_agg + n * HID);
    #pragma unroll
    for (int i = 0; i < 5; i++) t[i] = __ldg(ag + i);
    float* zt = (float*)t;

    float z[HID];
    #pragma unroll
    for (int k = 0; k < HID; k++) z[k] = fmaxf(zt[k] + sba[k], 0.0f);

    float z2[HID];
    #pragma unroll
    for (int j = 0; j < HID; j++) {
        float a = sbb[j];
        #pragma unroll
        for (int k = 0; k < HID; k++) a += z[k] * sWb[k * HID + j];
        z2[j] = fmaxf(a, 0.0f);
    }

    float ss = 0.0f;
    #pragma unroll
    for (int k = 0; k < HID; k++) ss += z2[k] * z2[k];
    float inv = 1.0f / fmaxf(sqrtf(ss), EPS_NORM);
    #pragma unroll
    for (int k = 0; k < HID; k++) z[k] = fmaxf(z2[k] * inv, 0.0f);  // h

    float o[HID];
    if (!write_h) {
        #pragma unroll
        for (int j = 0; j < HID; j++) {
            float a = 0.0f;
            #pragma unroll
            for (int k = 0; k < HID; k++) a += z[k] * sWn[k * HID + j];
            o[j] = a;
        }
    } else {
        #pragma unroll
        for (int j = 0; j < HID; j++) o[j] = z[j];
    }

    float* outp = write_h ? g_h : g_y;
    float4* op = (float4*)(outp + n * HID);
    #pragma unroll
    for (int i = 0; i < 5; i++) {
        float4 v;
        v.x = o[4 * i + 0]; v.y = o[4 * i + 1]; v.z = o[4 * i + 2]; v.w = o[4 * i + 3];
        op[i] = v;
    }
}

// ---------------- pooling: per-graph max / sum / count ---------------------
__global__ void k_pool(const void* __restrict__ batch_v) {
    int n = blockIdx.x * blockDim.x + threadIdx.x;
    bool valid = n < N_NODES;
    int g = -1;
    if (valid) {
        if (g_is64) g = (int)((const long long*)batch_v)[n];
        else        g = ((const int*)batch_v)[n];
    }
    float v[HID];
    if (valid) {
        const float4* hr = (const float4*)(g_h + (long long)n * HID);
        #pragma unroll
        for (int i = 0; i < 5; i++) {
            float4 t = __ldg(hr + i);
            v[4 * i] = t.x; v[4 * i + 1] = t.y; v[4 * i + 2] = t.z; v[4 * i + 3] = t.w;
        }
    } else {
        #pragma unroll
        for (int k = 0; k < HID; k++) v[k] = 0.0f;
    }

    const unsigned m = 0xffffffffu;
    int g0 = __shfl_sync(m, g, 0);
    bool uni = __all_sync(m, g == g0) && (g0 >= 0);
    int lane = threadIdx.x & 31;

    if (uni) {
        // batch is sorted; the vast majority of warps are graph-uniform.
        #pragma unroll
        for (int f = 0; f < HID; f++) {
            float s = v[f], mx = v[f];
            #pragma unroll
            for (int off = 16; off > 0; off >>= 1) {
                s  += __shfl_xor_sync(m, s, off);
                mx  = fmaxf(mx, __shfl_xor_sync(m, mx, off));
            }
            if (lane == 0) {
                atomicAdd(&g_psum[g0 * HID + f], s);
                atomicMax((int*)&g_pmax[g0 * HID + f], __float_as_int(mx));  // h >= 0
            }
        }
        if (lane == 0) atomicAdd(&g_cnt[g0], 32.0f);
    } else if (valid) {
        #pragma unroll
        for (int f = 0; f < HID; f++) {
            atomicAdd(&g_psum[g * HID + f], v[f]);
            atomicMax((int*)&g_pmax[g * HID + f], __float_as_int(v[f]));
        }
        atomicAdd(&g_cnt[g], 1.0f);
    }
}

// ---------------- final linear: [G, 40] @ [40, 10] + b ---------------------
__global__ void k_final(const float* __restrict__ Wlin, const float* __restrict__ blin,
                        float* __restrict__ out) {
    int idx = blockIdx.x * blockDim.x + threadIdx.x;
    if (idx >= N_GRAPHS * N_CLASSES) return;
    int gph = idx / N_CLASSES, c = idx % N_CLASSES;
    float cnt = g_cnt[gph];
    float icnt = 1.0f / fmaxf(cnt, 1.0f);
    float acc = __ldg(blin + c);
    #pragma unroll
    for (int k = 0; k < HID; k++) {
        float mx = (cnt > 0.0f) ? g_pmax[gph * HID + k] : 0.0f;
        float mean = g_psum[gph * HID + k] * icnt;
        acc += mx * __ldg(Wlin + k * N_CLASSES + c)
             + mean * __ldg(Wlin + (HID + k) * N_CLASSES + c);
    }
    out[idx] = acc;
}

// ---------------- launch ----------------------------------------------------
extern "C" void kernel_launch(void* const* d_in, const int* in_sizes, int n_in,
                              void* d_out, int out_size) {
    const float* x    = (const float*)d_in[0];
    const void*  ei   = d_in[1];
    const void*  batch= d_in[2];
    const float* ew   = (const float*)d_in[3];
    const float* W1a  = (const float*)d_in[4];
    const float* b1a  = (const float*)d_in[5];
    const float* W1b  = (const float*)d_in[6];
    const float* b1b  = (const float*)d_in[7];
    const float* W2a  = (const float*)d_in[8];
    const float* b2a  = (const float*)d_in[9];
    const float* W2b  = (const float*)d_in[10];
    const float* b2b  = (const float*)d_in[11];
    const float* W3a  = (const float*)d_in[12];
    const float* b3a  = (const float*)d_in[13];
    const float* W3b  = (const float*)d_in[14];
    const float* b3b  = (const float*)d_in[15];
    const float* Wlin = (const float*)d_in[16];
    const float* blin = (const float*)d_in[17];
    float* out = (float*)d_out;

    k_detect<<<1, 32>>>(ei);

    const int zag_grid = (N_NODES * HID + 1023) / 1024;
    const int sc_grid  = (N_EDGES + 255) / 256;
    const int mlp_grid = (N_NODES + 127) / 128;
    const int pool_grid = (N_NODES + 255) / 256;
    const int gemm_grid = (N_NODES + GEMM_NPB - 1) / GEMM_NPB;

    // layer 1 (Wa pre-applied before aggregation: agg(x)@Wa == agg(x@Wa))
    k_gemm_in<<<gemm_grid, 256>>>(x, W1a);
    k_zero_agg<<<zag_grid, 1024>>>();
    k_scatter<<<sc_grid, 256>>>(ei, ew);
    k_mlp<<<mlp_grid, 128>>>(b1a, W1b, b1b, W2a, 0);   // -> g_y = h1 @ W2a

    // layer 2
    k_zero_agg<<<zag_grid, 1024>>>();
    k_scatter<<<sc_grid, 256>>>(ei, ew);
    k_mlp<<<mlp_grid, 128>>>(b2a, W2b, b2b, W3a, 0);   // -> g_y = h2 @ W3a

    // layer 3
    k_zero_agg<<<zag_grid, 1024>>>();
    k_scatter<<<sc_grid, 256>>>(ei, ew);
    k_mlp<<<mlp_grid, 128>>>(b3a, W3b, b3b, nullptr, 1);  // -> g_h = h3

    // pooling + classifier
    k_zero_pool<<<3, 1024>>>();
    k_pool<<<pool_grid, 256>>>(batch);
    k_final<<<2, 640>>>(Wlin, blin, out);
}